// round 13
// baseline (speedup 1.0000x reference)
#include <cuda_runtime.h>

#define BB 4
#define NN 512
#define MM 512
#define LD 512
#define AG 256
#define ROWS (BB * NN)   // 2048

__device__ float g_dl[ROWS * AG];   // [row][a]
__device__ float g_cl[ROWS * AG];   // [row][a]

// pipeline flags (zero-init; self-reset at end of every launch)
__device__ int g_seq;        // number of batches whose proj is complete
__device__ int g_cnt[BB];    // per-batch proj arrival counters
__device__ int g_done;       // block completion counter

__device__ __forceinline__ float fast_tanh(float x) {
    float y;
    asm("tanh.approx.f32 %0, %1;" : "=f"(y) : "f"(x));
    return y;
}
__device__ __forceinline__ void ffma2(unsigned long long& d,
                                      unsigned long long a,
                                      unsigned long long b) {
    asm("fma.rn.f32x2 %0, %1, %2, %3;" : "=l"(d) : "l"(a), "l"(b), "l"(d));
}
__device__ __forceinline__ unsigned long long splat2(float x) {
    unsigned long long r;
    asm("mov.b64 %0, {%1, %1};" : "=l"(r) : "f"(x));
    return r;
}
__device__ __forceinline__ float2 unpack2(unsigned long long v) {
    float2 f;
    asm("mov.b64 {%0, %1}, %2;" : "=f"(f.x), "=f"(f.y) : "l"(v));
    return f;
}

// ---------------------------------------------------------------------------
// Fused pipelined kernel. 512 blocks x 256 threads; chunk b = blockIdx>>7.
// Phase 1 (proj): each block computes one 64x32 projection tile of batch b
//   (128 tiles = 2 gemms x 8 row-tiles x 8 col-tiles), fp32 FFMA2.
//   Proj of batch b starts only after batch b-1's proj is done (g_seq),
//   so proj_b overlaps dist_{b-1} (fma/LDS under MUFU).
// Phase 2 (dist): each block computes one 32(n) x 64(m) output tile of
//   batch b once g_seq >= b+1. MUFU-bound at the HW tanh floor.
// Deadlock-free: every wait depends only on strictly-lower-bid blocks.
// ---------------------------------------------------------------------------
__global__ __launch_bounds__(256, 4) void fused_kernel(
    const float* __restrict__ data, const float* __restrict__ crit,
    const float* __restrict__ Wl, const float* __restrict__ bl,
    const float* __restrict__ Wr, const float* __restrict__ br,
    const float* __restrict__ agg, float* __restrict__ out)
{
    __shared__ union {
        struct { float As[2][16][68]; float Bs[2][16][36]; } p;           // 13.3 KB
        struct { float dls[64][34]; float clsA[64][34];
                 float clsB[64][34]; float aggs[AG]; } d;                 // 27.1 KB
    } S;

    const int tid = threadIdx.x;
    const int b   = blockIdx.x >> 7;   // batch chunk 0..3
    const int i   = blockIdx.x & 127;  // index within chunk

    // ---- serialize proj across batches (creates the pipeline) ----
    if (b > 0) {
        if (tid == 0)
            while (*(volatile int*)&g_seq < b) __nanosleep(64);
        __syncthreads();
    }

    // =========================== PROJ PHASE ===============================
    {
        const int g    = i >> 6;                 // 0: data@Wl, 1: crit@Wr
        const int t    = i & 63;
        const int row0 = b * 512 + (t >> 3) * 64;
        const int col0 = (t & 7) * 32;

        const float* A    = g ? crit : data;
        const float* W    = g ? Wr   : Wl;
        const float* bias = g ? br   : bl;
        float*       outp = g ? g_cl : g_dl;

        const int ar = tid >> 2,  ac   = (tid & 3) << 2;   // A staging
        const int brow = tid >> 4, bcol = (tid & 15) << 1; // B staging
        const int rg = tid >> 4,  cg   = tid & 15;         // compute tile

        const float* Aptr = A + (size_t)(row0 + ar) * LD + ac;
        const float* Wptr = W + (size_t)brow * AG + col0 + bcol;

        unsigned long long a00 = 0ull, a01 = 0ull, a10 = 0ull, a11 = 0ull;

        {   // prologue: chunk 0 -> buf 0
            float4 av = *(const float4*)Aptr;
            S.p.As[0][ac + 0][ar] = av.x;  S.p.As[0][ac + 1][ar] = av.y;
            S.p.As[0][ac + 2][ar] = av.z;  S.p.As[0][ac + 3][ar] = av.w;
            *(float2*)&S.p.Bs[0][brow][bcol] = *(const float2*)Wptr;
        }
        __syncthreads();

        int cur = 0;
        for (int k0 = 0; k0 < LD; k0 += 16) {
            float4 an; float2 bn;
            const bool more = (k0 + 16) < LD;
            if (more) {
                an = *(const float4*)(Aptr + k0 + 16);
                bn = *(const float2*)(Wptr + (size_t)(k0 + 16) * AG);
            }
#pragma unroll
            for (int k = 0; k < 16; k++) {
                ulonglong2 aP = *(const ulonglong2*)&S.p.As[cur][k][rg << 2];
                float2 b2 = *(const float2*)&S.p.Bs[cur][k][cg << 1];
                unsigned long long s0 = splat2(b2.x);
                unsigned long long s1 = splat2(b2.y);
                ffma2(a00, aP.x, s0); ffma2(a01, aP.x, s1);
                ffma2(a10, aP.y, s0); ffma2(a11, aP.y, s1);
            }
            if (more) {
                int nxt = cur ^ 1;
                S.p.As[nxt][ac + 0][ar] = an.x;  S.p.As[nxt][ac + 1][ar] = an.y;
                S.p.As[nxt][ac + 2][ar] = an.z;  S.p.As[nxt][ac + 3][ar] = an.w;
                *(float2*)&S.p.Bs[nxt][brow][bcol] = bn;
                __syncthreads();
                cur = nxt;
            }
        }

        const float2 bv = *(const float2*)&bias[col0 + (cg << 1)];
        float2 x00 = unpack2(a00), x01 = unpack2(a01);
        float2 x10 = unpack2(a10), x11 = unpack2(a11);
        float* o = outp + (size_t)(row0 + (rg << 2)) * AG + col0 + (cg << 1);
        *(float2*)(o + 0 * AG) = make_float2(x00.x + bv.x, x01.x + bv.y);
        *(float2*)(o + 1 * AG) = make_float2(x00.y + bv.x, x01.y + bv.y);
        *(float2*)(o + 2 * AG) = make_float2(x10.x + bv.x, x11.x + bv.y);
        *(float2*)(o + 3 * AG) = make_float2(x10.y + bv.x, x11.y + bv.y);
    }

    __threadfence();     // publish proj stores before arrival
    __syncthreads();
    if (tid == 0) {
        if (atomicAdd(&g_cnt[b], 1) == 127)
            atomicExch(&g_seq, b + 1);             // batch b proj complete
        while (*(volatile int*)&g_seq < b + 1) __nanosleep(64);
    }
    __syncthreads();

    // =========================== DIST PHASE ===============================
    {
        const int n0  = (i >> 3) << 5;     // 16 n-tiles of 32
        const int m0  = (i & 7) << 6;      // 8 m-tiles of 64
        const int ty2 = (tid >> 4) << 1;   // n rows ty2, ty2+1
        const int tx4 = (tid & 15) << 2;   // m cols tx4..tx4+3

        const float* dlb = g_dl + (size_t)(b * NN + n0) * AG;
        const float* clb = g_cl + (size_t)(b * MM + m0) * AG;

        float a00 = 0.f, a01 = 0.f, a02 = 0.f, a03 = 0.f;
        float a10 = 0.f, a11 = 0.f, a12 = 0.f, a13 = 0.f;

        const float* dcol = &S.d.dls[0][ty2];
        const float* ccol = (tx4 < 32) ? &S.d.clsA[0][tx4] : &S.d.clsB[0][tx4 - 32];

        for (int a0 = 0; a0 < AG; a0 += 64) {
            __syncthreads();   // protect previous chunk reads / smem union
            if (a0 == 0) S.d.aggs[tid] = agg[tid];
            // stage dl: 32 rows x 64 a, transposed to a-major
#pragma unroll
            for (int h = 0; h < 2; h++) {
                int idx = tid + (h << 8);
                int r   = idx >> 4;            // 0..31
                int a4  = (idx & 15) << 2;     // 0..60
                float4 v = *(const float4*)(dlb + (size_t)r * AG + a0 + a4);
                S.d.dls[a4 + 0][r] = v.x;  S.d.dls[a4 + 1][r] = v.y;
                S.d.dls[a4 + 2][r] = v.z;  S.d.dls[a4 + 3][r] = v.w;
            }
            // stage cl: 64 rows x 64 a, split into two 32-wide arrays
#pragma unroll
            for (int h = 0; h < 4; h++) {
                int idx = tid + (h << 8);
                int r   = idx >> 4;            // 0..63
                int a4  = (idx & 15) << 2;
                float4 w = *(const float4*)(clb + (size_t)r * AG + a0 + a4);
                float (*cls)[34] = (r < 32) ? S.d.clsA : S.d.clsB;
                int rr = r & 31;
                cls[a4 + 0][rr] = w.x;  cls[a4 + 1][rr] = w.y;
                cls[a4 + 2][rr] = w.z;  cls[a4 + 3][rr] = w.w;
            }
            __syncthreads();

#pragma unroll 4
            for (int a = 0; a < 64; a++) {
                float2 d   = *(const float2*)(dcol + a * 34);
                float2 c01 = *(const float2*)(ccol + a * 34);
                float2 c23 = *(const float2*)(ccol + a * 34 + 2);
                float g = S.d.aggs[a0 + a];
                a00 = fmaf(fast_tanh(d.x + c01.x), g, a00);
                a01 = fmaf(fast_tanh(d.x + c01.y), g, a01);
                a02 = fmaf(fast_tanh(d.x + c23.x), g, a02);
                a03 = fmaf(fast_tanh(d.x + c23.y), g, a03);
                a10 = fmaf(fast_tanh(d.y + c01.x), g, a10);
                a11 = fmaf(fast_tanh(d.y + c01.y), g, a11);
                a12 = fmaf(fast_tanh(d.y + c23.x), g, a12);
                a13 = fmaf(fast_tanh(d.y + c23.y), g, a13);
            }
        }

        float* o = out + ((size_t)(b * NN + n0 + ty2) << 9) + m0 + tx4;
        *(float4*)o        = make_float4(a00, a01, a02, a03);
        *(float4*)(o + MM) = make_float4(a10, a11, a12, a13);
    }

    // ---- self-reset flags for the next graph replay ----
    __syncthreads();
    if (tid == 0) {
        __threadfence();
        if (atomicAdd(&g_done, 1) == 511) {
            g_seq  = 0;
            g_done = 0;
#pragma unroll
            for (int q = 0; q < BB; q++) g_cnt[q] = 0;
        }
    }
}

extern "C" void kernel_launch(void* const* d_in, const int* in_sizes, int n_in,
                              void* d_out, int out_size) {
    const float* data = (const float*)d_in[0];
    const float* crit = (const float*)d_in[1];
    const float* Wl   = (const float*)d_in[2];
    const float* bl   = (const float*)d_in[3];
    const float* Wr   = (const float*)d_in[4];
    const float* br   = (const float*)d_in[5];
    const float* agg  = (const float*)d_in[6];
    float* out = (float*)d_out;

    fused_kernel<<<512, 256>>>(data, crit, Wl, bl, Wr, br, agg, out);
}